// round 6
// baseline (speedup 1.0000x reference)
#include <cuda_runtime.h>
#include <cuda_bf16.h>
#include <cstdint>

#define D_MODEL 1024
#define NHEAD 16
#define DH 64
#define WIN 256
#define NB 2
#define NS 2048
#define MROWS (NB * NS)   // 4096

typedef __nv_bfloat16 bf16;

// 0.125 (1/sqrt(64)) * log2(e) — softmax computed in base-2 domain
#define SCALE2 0.1803368801111204f

// ---------------- device scratch (allocation-free rule) ----------------
__device__ bf16 g_Ahi[MROWS * D_MODEL];
__device__ bf16 g_Alo[MROWS * D_MODEL];
__device__ bf16 g_Whi[4096 * D_MODEL];     // [Wq;Wk;Wv;Wo]
__device__ bf16 g_Wlo[4096 * D_MODEL];
__device__ bf16 g_Qhi[MROWS * D_MODEL];    // [b,h,s,d]
__device__ bf16 g_Qlo[MROWS * D_MODEL];
__device__ bf16 g_Khi[MROWS * D_MODEL];
__device__ bf16 g_Klo[MROWS * D_MODEL];
__device__ bf16 g_Vhi[MROWS * D_MODEL];
__device__ bf16 g_Vlo[MROWS * D_MODEL];
__device__ bf16 g_Chi[MROWS * D_MODEL];    // attention ctx, [b,s,e]
__device__ bf16 g_Clo[MROWS * D_MODEL];

// ---------------- helpers (all baseline PTX, sm_80+) ----------------
__device__ __forceinline__ uint32_t smem_u32(const void* p) {
    uint32_t a;
    asm("{ .reg .u64 t; cvta.to.shared.u64 t, %1; cvt.u32.u64 %0, t; }" : "=r"(a) : "l"(p));
    return a;
}
__device__ __forceinline__ void cp16(uint32_t s, const void* g) {
    asm volatile("cp.async.cg.shared.global [%0], [%1], 16;" :: "r"(s), "l"(g));
}
#define CP_COMMIT() asm volatile("cp.async.commit_group;" ::: "memory")
#define CP_WAIT0()  asm volatile("cp.async.wait_group 0;" ::: "memory")

__device__ __forceinline__ void ldsm4(uint32_t* r, uint32_t a) {
    asm volatile("ldmatrix.sync.aligned.m8n8.x4.shared.b16 {%0,%1,%2,%3}, [%4];"
        : "=r"(r[0]), "=r"(r[1]), "=r"(r[2]), "=r"(r[3]) : "r"(a));
}
__device__ __forceinline__ void ldsm4t(uint32_t* r, uint32_t a) {
    asm volatile("ldmatrix.sync.aligned.m8n8.x4.trans.shared.b16 {%0,%1,%2,%3}, [%4];"
        : "=r"(r[0]), "=r"(r[1]), "=r"(r[2]), "=r"(r[3]) : "r"(a));
}
__device__ __forceinline__ void mma16816(float* c, const uint32_t* a, const uint32_t* b) {
    asm volatile("mma.sync.aligned.m16n8k16.row.col.f32.bf16.bf16.f32 "
        "{%0,%1,%2,%3}, {%4,%5,%6,%7}, {%8,%9}, {%0,%1,%2,%3};"
        : "+f"(c[0]), "+f"(c[1]), "+f"(c[2]), "+f"(c[3])
        : "r"(a[0]), "r"(a[1]), "r"(a[2]), "r"(a[3]), "r"(b[0]), "r"(b[1]));
}
__device__ __forceinline__ float ex2(float x) {
    float r;
    asm("ex2.approx.ftz.f32 %0, %1;" : "=f"(r) : "f"(x));
    return r;
}

// split two f32 into bf16x2 hi + bf16x2 lo (x0 in low half)
__device__ __forceinline__ void split_pack2(float x0, float x1, uint32_t& hi, uint32_t& lo) {
    __nv_bfloat162 h = __float22bfloat162_rn(make_float2(x0, x1));
    float h0 = __bfloat162float(h.x), h1 = __bfloat162float(h.y);
    __nv_bfloat162 l = __float22bfloat162_rn(make_float2(x0 - h0, x1 - h1));
    hi = *(uint32_t*)&h;
    lo = *(uint32_t*)&l;
}

// pad kernel: shifts ncu's -s 5 -c 1 capture window onto attn_mma
__global__ void nop_pad() {}

// ---------------- convert f32 -> bf16 hi/lo (X and stacked weights) ----------------
__global__ void __launch_bounds__(256) convert_all(const float* __restrict__ X,
                                                   const float* __restrict__ Wq,
                                                   const float* __restrict__ Wk,
                                                   const float* __restrict__ Wv,
                                                   const float* __restrict__ Wo)
{
    const size_t NA4 = (size_t)MROWS * D_MODEL / 4;
    size_t i4 = (size_t)blockIdx.x * blockDim.x + threadIdx.x;
    const float* src;
    bf16 *dh, *dl;
    size_t off;
    if (i4 < NA4) {
        off = i4 * 4;
        src = X + off;
        dh = g_Ahi; dl = g_Alo;
    } else {
        size_t j = (i4 - NA4) * 4;
        off = j;
        int row = (int)(j >> 10);
        int col = (int)(j & 1023);
        const float* W = (row < 1024) ? Wq : (row < 2048) ? Wk : (row < 3072) ? Wv : Wo;
        src = W + (size_t)(row & 1023) * D_MODEL + col;
        dh = g_Whi; dl = g_Wlo;
    }
    float4 v = *(const float4*)src;
    uint32_t h0, l0, h1, l1;
    split_pack2(v.x, v.y, h0, l0);
    split_pack2(v.z, v.w, h1, l1);
    *(uint2*)(dh + off) = make_uint2(h0, h1);
    *(uint2*)(dl + off) = make_uint2(l0, l1);
}

// ---------------- mma GEMM (unchanged, proven) ----------------
#define SROW 40
#define MAT_ELEMS (128 * SROW)
#define STAGE_ELEMS (4 * MAT_ELEMS)
#define GEMM_SMEM (2 * STAGE_ELEMS * 2)

__global__ void __launch_bounds__(256) gemm_mma(const bf16* __restrict__ Ahi,
                                                const bf16* __restrict__ Alo,
                                                int wrow0, int mode,
                                                float* __restrict__ out)
{
    extern __shared__ bf16 sm[];
    const int tid = threadIdx.x, lane = tid & 31, wid = tid >> 5;
    const int bm = blockIdx.y * 128, bn = blockIdx.x * 128;
    const bf16* Whi = g_Whi + (size_t)wrow0 * D_MODEL;
    const bf16* Wlo = g_Wlo + (size_t)wrow0 * D_MODEL;
    const uint32_t sbase = smem_u32(sm);

    float acc[4][4][4];
#pragma unroll
    for (int i = 0; i < 4; i++)
#pragma unroll
        for (int j = 0; j < 4; j++)
#pragma unroll
            for (int k = 0; k < 4; k++) acc[i][j][k] = 0.0f;

    const int wm = (wid & 1) * 64, wn = (wid >> 1) * 32;
    const int tg = lane & 3, rg = lane >> 2;

    {
#pragma unroll
        for (int m = 0; m < 4; m++) {
            const bf16* src = (m == 0) ? Ahi : (m == 1) ? Alo : (m == 2) ? Whi : Wlo;
            const int row0 = (m < 2) ? bm : bn;
#pragma unroll
            for (int r = 0; r < 2; r++) {
                int c = tid + r * 256;
                int row = c >> 2, cc = c & 3;
                cp16(sbase + (uint32_t)(m * MAT_ELEMS + row * SROW + cc * 8) * 2,
                     src + (size_t)(row0 + row) * D_MODEL + cc * 8);
            }
        }
        CP_COMMIT();
    }

    for (int kt = 0; kt < 32; kt++) {
        const int buf = kt & 1;
        CP_WAIT0();
        __syncthreads();
        if (kt + 1 < 32) {
            const int k0 = (kt + 1) * 32;
            const int nb = buf ^ 1;
#pragma unroll
            for (int m = 0; m < 4; m++) {
                const bf16* src = (m == 0) ? Ahi : (m == 1) ? Alo : (m == 2) ? Whi : Wlo;
                const int row0 = (m < 2) ? bm : bn;
#pragma unroll
                for (int r = 0; r < 2; r++) {
                    int c = tid + r * 256;
                    int row = c >> 2, cc = c & 3;
                    cp16(sbase + (uint32_t)(nb * STAGE_ELEMS + m * MAT_ELEMS + row * SROW + cc * 8) * 2,
                         src + (size_t)(row0 + row) * D_MODEL + k0 + cc * 8);
                }
            }
            CP_COMMIT();
        }
        const uint32_t sA = sbase + (uint32_t)(buf * STAGE_ELEMS) * 2;
#pragma unroll
        for (int kk = 0; kk < 32; kk += 16) {
            uint32_t ah[4][4], al[4][4];
#pragma unroll
            for (int mi = 0; mi < 4; mi++) {
                uint32_t ad = sA + (uint32_t)((wm + mi * 16 + (lane & 15)) * SROW + kk + (lane >> 4) * 8) * 2;
                ldsm4(ah[mi], ad);
                ldsm4(al[mi], ad + MAT_ELEMS * 2);
            }
            uint32_t bh[4][2], bl[4][2];
            const int g4 = lane >> 3;
#pragma unroll
            for (int np = 0; np < 4; np += 2) {
                uint32_t bd = sA + (uint32_t)(2 * MAT_ELEMS +
                    (wn + (np + (g4 >> 1)) * 8 + (lane & 7)) * SROW + kk + (g4 & 1) * 8) * 2;
                uint32_t t[4];
                ldsm4(t, bd);
                bh[np][0] = t[0]; bh[np][1] = t[1]; bh[np + 1][0] = t[2]; bh[np + 1][1] = t[3];
                ldsm4(t, bd + MAT_ELEMS * 2);
                bl[np][0] = t[0]; bl[np][1] = t[1]; bl[np + 1][0] = t[2]; bl[np + 1][1] = t[3];
            }
#pragma unroll
            for (int mi = 0; mi < 4; mi++)
#pragma unroll
                for (int ni = 0; ni < 4; ni++) {
                    mma16816(acc[mi][ni], ah[mi], bh[ni]);
                    mma16816(acc[mi][ni], ah[mi], bl[ni]);
                    mma16816(acc[mi][ni], al[mi], bh[ni]);
                }
        }
        __syncthreads();
    }

#pragma unroll
    for (int mi = 0; mi < 4; mi++) {
        const int mrow0 = bm + wm + mi * 16 + rg;
#pragma unroll
        for (int ni = 0; ni < 4; ni++) {
            const int ngl = bn + wn + ni * 8 + tg * 2;
#pragma unroll
            for (int r = 0; r < 2; r++) {
                const int m = mrow0 + r * 8;
                const float x0 = acc[mi][ni][r * 2], x1 = acc[mi][ni][r * 2 + 1];
                if (mode == 0) {
                    const int mat = ngl >> 10, e = ngl & 1023, hh = e >> 6, dd = e & 63;
                    const int bb = m >> 11, ss = m & (NS - 1);
                    const size_t off = ((size_t)(bb * NHEAD + hh) * NS + ss) * DH + dd;
                    uint32_t hi, lo;
                    split_pack2(x0, x1, hi, lo);
                    bf16 *ph, *pl;
                    if (mat == 0)      { ph = g_Qhi; pl = g_Qlo; }
                    else if (mat == 1) { ph = g_Khi; pl = g_Klo; }
                    else               { ph = g_Vhi; pl = g_Vlo; }
                    *(uint32_t*)(ph + off) = hi;
                    *(uint32_t*)(pl + off) = lo;
                } else {
                    *(float2*)(out + (size_t)m * D_MODEL + ngl) = make_float2(x0, x1);
                }
            }
        }
    }
}

// ---------------- attention v4: reg-pressure relief + 1 barrier/tile ----------------
#define KROW 72
#define AMAT_B (64 * KROW * 2)          // 9216 B per matrix
#define ASTAGE_B (4 * AMAT_B)           // 36864 B per stage
#define ATTN_SMEM (2 * ASTAGE_B)        // 73728 B dynamic

__global__ void __launch_bounds__(128) attn_mma(const int* __restrict__ amask)
{
    extern __shared__ char dynsm[];
    __shared__ float smask[2][64];

    const int tid = threadIdx.x, lane = tid & 31, wid = tid >> 5;
    const int tg = lane & 3, rg = lane >> 2;
    // longest-first: high i0 CTAs (most key tiles) launch first
    const int i0 = (gridDim.x - 1 - blockIdx.x) * 64;
    const int h = blockIdx.y, b = blockIdx.z;
    const size_t base = ((size_t)(b * NHEAD + h)) * NS * DH;
    const uint32_t sbase = smem_u32(dynsm);

    // ---- stage Q (64x64 hi/lo) through stage-0 mats 0/1, ldmatrix to regs ----
#pragma unroll
    for (int i = 0; i < 4; i++) {
        int c = tid + i * 128;              // 0..511 = 64 rows x 8 chunks
        int row = c >> 3, cc = c & 7;
        const size_t g = base + (size_t)(i0 + row) * DH + cc * 8;
        const uint32_t so = (uint32_t)(row * KROW + cc * 8) * 2;
        cp16(sbase + so, g_Qhi + g);
        cp16(sbase + AMAT_B + so, g_Qlo + g);
    }
    CP_COMMIT();
    CP_WAIT0();
    __syncthreads();

    const int m0 = wid * 16;
    uint32_t qh[4][4], ql[4][4];
#pragma unroll
    for (int u = 0; u < 4; u++) {
        const uint32_t off = (uint32_t)((m0 + (lane & 15)) * KROW + u * 16 + (lane >> 4) * 8) * 2;
        ldsm4(qh[u], sbase + off);
        ldsm4(ql[u], sbase + AMAT_B + off);
    }
    __syncthreads();   // all warps done reading Q before stage-0 K/V overwrite

    float o[8][4];
#pragma unroll
    for (int i = 0; i < 8; i++)
#pragma unroll
        for (int j = 0; j < 4; j++) o[i][j] = 0.0f;
    float mrow[2] = {-1e30f, -1e30f}, lrow[2] = {0.0f, 0.0f};

    const int jlast = min(i0 + 63 + (WIN - 1), NS - 1) >> 6;

    auto load_stage = [&](int j0, int bufs) {
        const uint32_t st = sbase + (uint32_t)bufs * ASTAGE_B;
#pragma unroll
        for (int i = 0; i < 16; i++) {
            int c = tid + i * 128;           // 0..2047 = 4 mats x 64 rows x 8 chunks
            int mat = c >> 9;
            int idx = c & 511;
            int row = idx >> 3, cc = idx & 7;
            const size_t g = base + (size_t)(j0 + row) * DH + cc * 8;
            const bf16* src = (mat == 0) ? g_Khi : (mat == 1) ? g_Klo
                            : (mat == 2) ? g_Vhi : g_Vlo;
            cp16(st + (uint32_t)mat * AMAT_B + (uint32_t)(row * KROW + cc * 8) * 2, src + g);
        }
        if (tid < 64)
            smask[bufs][tid] = (amask[b * NS + j0 + tid] != 0) ? 0.0f : -1e30f;
    };

    // prologue: stage 0 in flight
    load_stage(0, 0);
    CP_COMMIT();

    for (int t = 0; t <= jlast; t++) {
        const int buf = t & 1;
        // single sync point per tile:
        //  - my cp.async group for tile t is complete (wait) and visible to all (sync)
        //  - all warps have finished compute on buf^1 (tile t-1), so it may be reloaded
        CP_WAIT0();
        __syncthreads();
        if (t < jlast) {
            load_stage((t + 1) * 64, buf ^ 1);
            CP_COMMIT();
        }

        const uint32_t st = sbase + (uint32_t)buf * ASTAGE_B;
        const uint32_t skh = st, skl = st + AMAT_B, svh = st + 2 * AMAT_B, svl = st + 3 * AMAT_B;
        const int j0 = t * 64;

        // ---- S = Q K^T ----
        float sc[8][4];
#pragma unroll
        for (int i = 0; i < 8; i++)
#pragma unroll
            for (int j = 0; j < 4; j++) sc[i][j] = 0.0f;

        const int g4 = lane >> 3;
#pragma unroll
        for (int u = 0; u < 4; u++) {
#pragma unroll
            for (int np = 0; np < 8; np += 2) {
                const uint32_t bd = (uint32_t)(((np + (g4 >> 1)) * 8 + (lane & 7)) * KROW
                                               + u * 16 + (g4 & 1) * 8) * 2;
                uint32_t th[4], tl[4];
                ldsm4(th, skh + bd);
                ldsm4(tl, skl + bd);
                mma16816(sc[np], qh[u], &th[0]);
                mma16816(sc[np], qh[u], &tl[0]);
                mma16816(sc[np], ql[u], &th[0]);
                mma16816(sc[np + 1], qh[u], &th[2]);
                mma16816(sc[np + 1], qh[u], &tl[2]);
                mma16816(sc[np + 1], ql[u], &th[2]);
            }
        }

        // ---- mask + scale (base-2 domain) + online softmax ----
        // interior tile iff max jg (j0+63) <= min ig (i0+m0) + WIN-1
        const bool interior = (j0 <= i0 + m0 + (WIN - 1) - 63);

#pragma unroll
        for (int r = 0; r < 2; r++) {
            float rmax = -1e30f;
            if (interior) {
#pragma unroll
                for (int nt = 0; nt < 8; nt++) {
                    const float2 mk = *(const float2*)&smask[buf][nt * 8 + tg * 2];
                    float s0 = fmaf(sc[nt][r * 2 + 0], SCALE2, mk.x);
                    float s1 = fmaf(sc[nt][r * 2 + 1], SCALE2, mk.y);
                    sc[nt][r * 2 + 0] = s0;
                    sc[nt][r * 2 + 1] = s1;
                    rmax = fmaxf(rmax, fmaxf(s0, s1));
                }
            } else {
                const int ig = i0 + m0 + rg + r * 8;
#pragma unroll
                for (int nt = 0; nt < 8; nt++) {
                    const float2 mk = *(const float2*)&smask[buf][nt * 8 + tg * 2];
#pragma unroll
                    for (int e = 0; e < 2; e++) {
                        const int jg = j0 + nt * 8 + tg * 2 + e;
                        float s = fmaf(sc[nt][r * 2 + e], SCALE2, (e == 0) ? mk.x : mk.y);
                        if (jg - ig > (WIN - 1)) s = -1e30f;
                        sc[nt][r * 2 + e] = s;
                        rmax = fmaxf(rmax, s);
                    }
                }
            }
            rmax = fmaxf(rmax, __shfl_xor_sync(0xffffffffu, rmax, 1));
            rmax = fmaxf(rmax, __shfl_xor_sync(0xffffffffu, rmax, 2));
            const float mnew = fmaxf(mrow[r], rmax);
            const float alpha = ex2(mrow[r] - mnew);
            float rsum = 0.0f;
#pragma unroll
            for (int nt = 0; nt < 8; nt++)
#pragma unroll
                for (int e = 0; e < 2; e++) {
                    const float p = ex2(sc[nt][r * 2 + e] - mnew);
                    sc[nt][r * 2 + e] = p;
                    rsum += p;
                }
            rsum += __shfl_xor_sync(0xffffffffu, rsum, 1);
            rsum += __shfl_xor_sync(0xffffffffu, rsum, 2);
            lrow[r] = lrow[r] * alpha + rsum;
            mrow[r] = mnew;
#pragma unroll
            for (int nt = 0; nt < 8; nt++) {
                o[nt][r * 2 + 0] *= alpha;
                o[nt][r * 2 + 1] *= alpha;
            }
        }

        // ---- O += P V  (P split computed per-u to cap register pressure) ----
#pragma unroll
        for (int u = 0; u < 4; u++) {
            uint32_t ph[4], pl[4];
            split_pack2(sc[2 * u][0],     sc[2 * u][1],     ph[0], pl[0]);
            split_pack2(sc[2 * u][2],     sc[2 * u][3],     ph[1], pl[1]);
            split_pack2(sc[2 * u + 1][0], sc[2 * u + 1][1], ph[2], pl[2]);
            split_pack2(sc[2 * u + 1][2], sc[2 * u + 1][3], ph[3], pl[3]);
#pragma unroll
            for (int np = 0; np < 8; np += 2) {
                const uint32_t bd = (uint32_t)((u * 16 + (g4 & 1) * 8 + (lane & 7)) * KROW
                                               + (np + (g4 >> 1)) * 8) * 2;
                uint32_t th[4], tl[4];
                ldsm4t(th, svh + bd);
                ldsm4t(tl, svl + bd);
                mma16816(o[np], ph, &th[0]);
                mma16816(o[np], ph, &tl[0]);
                mma16816(o[np], pl, &th[0]);
                mma16816(o[np + 1], ph, &th[2]);
                mma16816(o[np + 1], ph, &tl[2]);
                mma16816(o[np + 1], pl, &th[2]);
            }
        }
    }

    // ---- epilogue: ctx as bf16 hi/lo [b,s,e] ----
#pragma unroll
    for (int r = 0; r < 2; r++) {
        const float inv = 1.0f / lrow[r];
        const int s_g = i0 + m0 + rg + r * 8;
        const size_t rowoff = ((size_t)b * NS + s_g) * D_MODEL + h * DH;
#pragma unroll
        for (int nt = 0; nt < 8; nt++) {
            uint32_t hi, lo;
            split_pack2(o[nt][r * 2] * inv, o[nt][r * 2 + 1] * inv, hi, lo);
            const size_t off = rowoff + nt * 8 + tg * 2;
            *(uint32_t*)(g_Chi + off) = hi;
            *(uint32_t*)(g_Clo + off) = lo;
        }
    }
}

// ---------------- host launcher ----------------
extern "C" void kernel_launch(void* const* d_in, const int* in_sizes, int n_in,
                              void* d_out, int out_size)
{
    const float* hidden = (const float*)d_in[0];
    const int* amask    = (const int*)d_in[1];
    const float* Wq     = (const float*)d_in[2];
    const float* Wk     = (const float*)d_in[3];
    const float* Wv     = (const float*)d_in[4];
    const float* Wo     = (const float*)d_in[5];
    float* out = (float*)d_out;

    static int attr_set = 0;
    if (!attr_set) {
        cudaFuncSetAttribute(gemm_mma, cudaFuncAttributeMaxDynamicSharedMemorySize, GEMM_SMEM);
        cudaFuncSetAttribute(attn_mma, cudaFuncAttributeMaxDynamicSharedMemorySize, ATTN_SMEM);
        attr_set = 1;
    }

    bf16 *pAhi, *pAlo, *pChi, *pClo;
    cudaGetSymbolAddress((void**)&pAhi, g_Ahi);
    cudaGetSymbolAddress((void**)&pAlo, g_Alo);
    cudaGetSymbolAddress((void**)&pChi, g_Chi);
    cudaGetSymbolAddress((void**)&pClo, g_Clo);

    // pads: make attn_mma global launch #6 so ncu (-s 5 -c 1) profiles it
    nop_pad<<<1, 32>>>();
    nop_pad<<<1, 32>>>();
    nop_pad<<<1, 32>>>();

    // 1. f32 -> bf16 hi/lo (X + stacked weights)
    convert_all<<<2 * (MROWS * D_MODEL / 4) / 256, 256>>>(hidden, Wq, Wk, Wv, Wo);

    // 2. fused QKV projection (N = 3072), scatter bf16 Q/K/V
    gemm_mma<<<dim3(3 * D_MODEL / 128, MROWS / 128), 256, GEMM_SMEM>>>(pAhi, pAlo, 0, 0, nullptr);

    // 3. attention (64q tiles, double-buffered, 1 barrier/tile)
    attn_mma<<<dim3(NS / 64, NHEAD, NB), 128, ATTN_SMEM>>>(amask);

    // 4. output projection (weight rows 3072..4095), f32 out
    gemm_mma<<<dim3(D_MODEL / 128, MROWS / 128), 256, GEMM_SMEM>>>(pChi, pClo, 3 * D_MODEL, 1, out);
}

// round 7
// speedup vs baseline: 1.0224x; 1.0224x over previous
#include <cuda_runtime.h>
#include <cuda_bf16.h>
#include <cstdint>

#define D_MODEL 1024
#define NHEAD 16
#define DH 64
#define WIN 256
#define NB 2
#define NS 2048
#define MROWS (NB * NS)   // 4096

typedef __nv_bfloat16 bf16;

// 0.125 (1/sqrt(64)) * log2(e) — softmax computed in base-2 domain
#define SCALE2 0.1803368801111204f

// ---------------- device scratch (allocation-free rule) ----------------
__device__ bf16 g_Ahi[MROWS * D_MODEL];
__device__ bf16 g_Alo[MROWS * D_MODEL];
__device__ bf16 g_Whi[4096 * D_MODEL];     // [Wq;Wk;Wv;Wo]
__device__ bf16 g_Wlo[4096 * D_MODEL];
__device__ bf16 g_Qhi[MROWS * D_MODEL];    // [b,h,s,d]
__device__ bf16 g_Qlo[MROWS * D_MODEL];
__device__ bf16 g_Khi[MROWS * D_MODEL];
__device__ bf16 g_Klo[MROWS * D_MODEL];
__device__ bf16 g_Vhi[MROWS * D_MODEL];
__device__ bf16 g_Vlo[MROWS * D_MODEL];
__device__ bf16 g_Chi[MROWS * D_MODEL];    // attention ctx, [b,s,e]
__device__ bf16 g_Clo[MROWS * D_MODEL];

// ---------------- helpers (all baseline PTX, sm_80+) ----------------
__device__ __forceinline__ uint32_t smem_u32(const void* p) {
    uint32_t a;
    asm("{ .reg .u64 t; cvta.to.shared.u64 t, %1; cvt.u32.u64 %0, t; }" : "=r"(a) : "l"(p));
    return a;
}
__device__ __forceinline__ void cp16(uint32_t s, const void* g) {
    asm volatile("cp.async.cg.shared.global [%0], [%1], 16;" :: "r"(s), "l"(g));
}
#define CP_COMMIT() asm volatile("cp.async.commit_group;" ::: "memory")
#define CP_WAIT0()  asm volatile("cp.async.wait_group 0;" ::: "memory")

__device__ __forceinline__ void ldsm4(uint32_t* r, uint32_t a) {
    asm volatile("ldmatrix.sync.aligned.m8n8.x4.shared.b16 {%0,%1,%2,%3}, [%4];"
        : "=r"(r[0]), "=r"(r[1]), "=r"(r[2]), "=r"(r[3]) : "r"(a));
}
__device__ __forceinline__ void ldsm4t(uint32_t* r, uint32_t a) {
    asm volatile("ldmatrix.sync.aligned.m8n8.x4.trans.shared.b16 {%0,%1,%2,%3}, [%4];"
        : "=r"(r[0]), "=r"(r[1]), "=r"(r[2]), "=r"(r[3]) : "r"(a));
}
__device__ __forceinline__ void mma16816(float* c, const uint32_t* a, const uint32_t* b) {
    asm volatile("mma.sync.aligned.m16n8k16.row.col.f32.bf16.bf16.f32 "
        "{%0,%1,%2,%3}, {%4,%5,%6,%7}, {%8,%9}, {%0,%1,%2,%3};"
        : "+f"(c[0]), "+f"(c[1]), "+f"(c[2]), "+f"(c[3])
        : "r"(a[0]), "r"(a[1]), "r"(a[2]), "r"(a[3]), "r"(b[0]), "r"(b[1]));
}
__device__ __forceinline__ float ex2(float x) {
    float r;
    asm("ex2.approx.ftz.f32 %0, %1;" : "=f"(r) : "f"(x));
    return r;
}

// split two f32 into bf16x2 hi + bf16x2 lo (x0 in low half)
__device__ __forceinline__ void split_pack2(float x0, float x1, uint32_t& hi, uint32_t& lo) {
    __nv_bfloat162 h = __float22bfloat162_rn(make_float2(x0, x1));
    float h0 = __bfloat162float(h.x), h1 = __bfloat162float(h.y);
    __nv_bfloat162 l = __float22bfloat162_rn(make_float2(x0 - h0, x1 - h1));
    hi = *(uint32_t*)&h;
    lo = *(uint32_t*)&l;
}

// pad kernel: the profiler captures the 4th launch; one pad puts attn_mma there
__global__ void nop_pad() {}

// ---------------- convert f32 -> bf16 hi/lo (X and stacked weights) ----------------
__global__ void __launch_bounds__(256) convert_all(const float* __restrict__ X,
                                                   const float* __restrict__ Wq,
                                                   const float* __restrict__ Wk,
                                                   const float* __restrict__ Wv,
                                                   const float* __restrict__ Wo)
{
    const size_t NA4 = (size_t)MROWS * D_MODEL / 4;
    size_t i4 = (size_t)blockIdx.x * blockDim.x + threadIdx.x;
    const float* src;
    bf16 *dh, *dl;
    size_t off;
    if (i4 < NA4) {
        off = i4 * 4;
        src = X + off;
        dh = g_Ahi; dl = g_Alo;
    } else {
        size_t j = (i4 - NA4) * 4;
        off = j;
        int row = (int)(j >> 10);
        int col = (int)(j & 1023);
        const float* W = (row < 1024) ? Wq : (row < 2048) ? Wk : (row < 3072) ? Wv : Wo;
        src = W + (size_t)(row & 1023) * D_MODEL + col;
        dh = g_Whi; dl = g_Wlo;
    }
    float4 v = *(const float4*)src;
    uint32_t h0, l0, h1, l1;
    split_pack2(v.x, v.y, h0, l0);
    split_pack2(v.z, v.w, h1, l1);
    *(uint2*)(dh + off) = make_uint2(h0, h1);
    *(uint2*)(dl + off) = make_uint2(l0, l1);
}

// ---------------- GEMM v2: 128x128 CTA tile, 4 warps, warp tile 64x64 ----------------
// C[m,n] = sum_k A[m,k] * W[n,k]; 3-pass bf16 split; BK=32 double-buffered; 1 sync/kt.
#define SROW 40                 // 32 + 8 pad (bf16 elems per smem row)
#define MAT_ELEMS (128 * SROW)  // 5120
#define STAGE_ELEMS (4 * MAT_ELEMS)
#define GEMM_SMEM (2 * STAGE_ELEMS * 2)  // 81920 B

__global__ void __launch_bounds__(128) gemm_mma(const bf16* __restrict__ Ahi,
                                                const bf16* __restrict__ Alo,
                                                int wrow0, int mode,
                                                float* __restrict__ out)
{
    extern __shared__ bf16 sm[];
    const int tid = threadIdx.x, lane = tid & 31, wid = tid >> 5;
    const int bm = blockIdx.y * 128, bn = blockIdx.x * 128;
    const bf16* Whi = g_Whi + (size_t)wrow0 * D_MODEL;
    const bf16* Wlo = g_Wlo + (size_t)wrow0 * D_MODEL;
    const uint32_t sbase = smem_u32(sm);

    float acc[4][8][4];
#pragma unroll
    for (int i = 0; i < 4; i++)
#pragma unroll
        for (int j = 0; j < 8; j++)
#pragma unroll
            for (int k = 0; k < 4; k++) acc[i][j][k] = 0.0f;

    const int wm = (wid & 1) * 64, wn = (wid >> 1) * 64;
    const int tg = lane & 3, rg = lane >> 2;
    const int g4 = lane >> 3;

    // stage loader: 4 mats x 128 rows x 4 16B-chunks = 2048 cp16 / 128 threads
    auto load_stage = [&](int k0, int bufs) {
        const uint32_t st = sbase + (uint32_t)(bufs * STAGE_ELEMS) * 2;
#pragma unroll
        for (int i = 0; i < 16; i++) {
            int c = tid + i * 128;
            int mat = c >> 9;
            int idx = c & 511;
            int row = idx >> 2, cc = idx & 3;
            const bf16* src = (mat == 0) ? Ahi : (mat == 1) ? Alo : (mat == 2) ? Whi : Wlo;
            const int row0 = (mat < 2) ? bm : bn;
            cp16(st + (uint32_t)(mat * MAT_ELEMS + row * SROW + cc * 8) * 2,
                 src + (size_t)(row0 + row) * D_MODEL + k0 + cc * 8);
        }
    };

    load_stage(0, 0);
    CP_COMMIT();

    for (int kt = 0; kt < 32; kt++) {
        const int buf = kt & 1;
        CP_WAIT0();
        __syncthreads();           // kt data visible; all warps done with buf^1 (kt-1)
        if (kt + 1 < 32) {
            load_stage((kt + 1) * 32, buf ^ 1);
            CP_COMMIT();
        }

        const uint32_t sA = sbase + (uint32_t)(buf * STAGE_ELEMS) * 2;
#pragma unroll
        for (int kk = 0; kk < 32; kk += 16) {
            uint32_t ah[4][4], al[4][4];
#pragma unroll
            for (int mi = 0; mi < 4; mi++) {
                uint32_t ad = sA + (uint32_t)((wm + mi * 16 + (lane & 15)) * SROW + kk + (lane >> 4) * 8) * 2;
                ldsm4(ah[mi], ad);
                ldsm4(al[mi], ad + MAT_ELEMS * 2);
            }
            // two 32-wide N halves to bound register pressure
#pragma unroll
            for (int nh = 0; nh < 2; nh++) {
                uint32_t bh[4][2], bl[4][2];
#pragma unroll
                for (int np = 0; np < 4; np += 2) {
                    uint32_t bd = sA + (uint32_t)(2 * MAT_ELEMS +
                        (wn + nh * 32 + (np + (g4 >> 1)) * 8 + (lane & 7)) * SROW + kk + (g4 & 1) * 8) * 2;
                    uint32_t t[4];
                    ldsm4(t, bd);
                    bh[np][0] = t[0]; bh[np][1] = t[1]; bh[np + 1][0] = t[2]; bh[np + 1][1] = t[3];
                    ldsm4(t, bd + MAT_ELEMS * 2);
                    bl[np][0] = t[0]; bl[np][1] = t[1]; bl[np + 1][0] = t[2]; bl[np + 1][1] = t[3];
                }
#pragma unroll
                for (int mi = 0; mi < 4; mi++)
#pragma unroll
                    for (int ni = 0; ni < 4; ni++) {
                        float* a2 = acc[mi][nh * 4 + ni];
                        mma16816(a2, ah[mi], bh[ni]);
                        mma16816(a2, ah[mi], bl[ni]);
                        mma16816(a2, al[mi], bh[ni]);
                    }
            }
        }
    }

    // epilogue
#pragma unroll
    for (int mi = 0; mi < 4; mi++) {
        const int mrow0 = bm + wm + mi * 16 + rg;
#pragma unroll
        for (int ni = 0; ni < 8; ni++) {
            const int ngl = bn + wn + ni * 8 + tg * 2;
#pragma unroll
            for (int r = 0; r < 2; r++) {
                const int m = mrow0 + r * 8;
                const float x0 = acc[mi][ni][r * 2], x1 = acc[mi][ni][r * 2 + 1];
                if (mode == 0) {
                    const int mat = ngl >> 10, e = ngl & 1023, hh = e >> 6, dd = e & 63;
                    const int bb = m >> 11, ss = m & (NS - 1);
                    const size_t off = ((size_t)(bb * NHEAD + hh) * NS + ss) * DH + dd;
                    uint32_t hi, lo;
                    split_pack2(x0, x1, hi, lo);
                    bf16 *ph, *pl;
                    if (mat == 0)      { ph = g_Qhi; pl = g_Qlo; }
                    else if (mat == 1) { ph = g_Khi; pl = g_Klo; }
                    else               { ph = g_Vhi; pl = g_Vlo; }
                    *(uint32_t*)(ph + off) = hi;
                    *(uint32_t*)(pl + off) = lo;
                } else {
                    *(float2*)(out + (size_t)m * D_MODEL + ngl) = make_float2(x0, x1);
                }
            }
        }
    }
}

// ---------------- attention (unchanged from round 6) ----------------
#define KROW 72
#define AMAT_B (64 * KROW * 2)          // 9216 B per matrix
#define ASTAGE_B (4 * AMAT_B)           // 36864 B per stage
#define ATTN_SMEM (2 * ASTAGE_B)        // 73728 B dynamic

__global__ void __launch_bounds__(128) attn_mma(const int* __restrict__ amask)
{
    extern __shared__ char dynsm[];
    __shared__ float smask[2][64];

    const int tid = threadIdx.x, lane = tid & 31, wid = tid >> 5;
    const int tg = lane & 3, rg = lane >> 2;
    const int i0 = (gridDim.x - 1 - blockIdx.x) * 64;
    const int h = blockIdx.y, b = blockIdx.z;
    const size_t base = ((size_t)(b * NHEAD + h)) * NS * DH;
    const uint32_t sbase = smem_u32(dynsm);

#pragma unroll
    for (int i = 0; i < 4; i++) {
        int c = tid + i * 128;
        int row = c >> 3, cc = c & 7;
        const size_t g = base + (size_t)(i0 + row) * DH + cc * 8;
        const uint32_t so = (uint32_t)(row * KROW + cc * 8) * 2;
        cp16(sbase + so, g_Qhi + g);
        cp16(sbase + AMAT_B + so, g_Qlo + g);
    }
    CP_COMMIT();
    CP_WAIT0();
    __syncthreads();

    const int m0 = wid * 16;
    uint32_t qh[4][4], ql[4][4];
#pragma unroll
    for (int u = 0; u < 4; u++) {
        const uint32_t off = (uint32_t)((m0 + (lane & 15)) * KROW + u * 16 + (lane >> 4) * 8) * 2;
        ldsm4(qh[u], sbase + off);
        ldsm4(ql[u], sbase + AMAT_B + off);
    }
    __syncthreads();

    float o[8][4];
#pragma unroll
    for (int i = 0; i < 8; i++)
#pragma unroll
        for (int j = 0; j < 4; j++) o[i][j] = 0.0f;
    float mrow[2] = {-1e30f, -1e30f}, lrow[2] = {0.0f, 0.0f};

    const int jlast = min(i0 + 63 + (WIN - 1), NS - 1) >> 6;

    auto load_stage = [&](int j0, int bufs) {
        const uint32_t st = sbase + (uint32_t)bufs * ASTAGE_B;
#pragma unroll
        for (int i = 0; i < 16; i++) {
            int c = tid + i * 128;
            int mat = c >> 9;
            int idx = c & 511;
            int row = idx >> 3, cc = idx & 7;
            const size_t g = base + (size_t)(j0 + row) * DH + cc * 8;
            const bf16* src = (mat == 0) ? g_Khi : (mat == 1) ? g_Klo
                            : (mat == 2) ? g_Vhi : g_Vlo;
            cp16(st + (uint32_t)mat * AMAT_B + (uint32_t)(row * KROW + cc * 8) * 2, src + g);
        }
        if (tid < 64)
            smask[bufs][tid] = (amask[b * NS + j0 + tid] != 0) ? 0.0f : -1e30f;
    };

    load_stage(0, 0);
    CP_COMMIT();

    for (int t = 0; t <= jlast; t++) {
        const int buf = t & 1;
        CP_WAIT0();
        __syncthreads();
        if (t < jlast) {
            load_stage((t + 1) * 64, buf ^ 1);
            CP_COMMIT();
        }

        const uint32_t st = sbase + (uint32_t)buf * ASTAGE_B;
        const uint32_t skh = st, skl = st + AMAT_B, svh = st + 2 * AMAT_B, svl = st + 3 * AMAT_B;
        const int j0 = t * 64;

        float sc[8][4];
#pragma unroll
        for (int i = 0; i < 8; i++)
#pragma unroll
            for (int j = 0; j < 4; j++) sc[i][j] = 0.0f;

        const int g4 = lane >> 3;
#pragma unroll
        for (int u = 0; u < 4; u++) {
#pragma unroll
            for (int np = 0; np < 8; np += 2) {
                const uint32_t bd = (uint32_t)(((np + (g4 >> 1)) * 8 + (lane & 7)) * KROW
                                               + u * 16 + (g4 & 1) * 8) * 2;
                uint32_t th[4], tl[4];
                ldsm4(th, skh + bd);
                ldsm4(tl, skl + bd);
                mma16816(sc[np], qh[u], &th[0]);
                mma16816(sc[np], qh[u], &tl[0]);
                mma16816(sc[np], ql[u], &th[0]);
                mma16816(sc[np + 1], qh[u], &th[2]);
                mma16816(sc[np + 1], qh[u], &tl[2]);
                mma16816(sc[np + 1], ql[u], &th[2]);
            }
        }

        const bool interior = (j0 <= i0 + m0 + (WIN - 1) - 63);

#pragma unroll
        for (int r = 0; r < 2; r++) {
            float rmax = -1e30f;
            if (interior) {
#pragma unroll
                for (int nt = 0; nt < 8; nt++) {
                    const float2 mk = *(const float2*)&smask[buf][nt * 8 + tg * 2];
                    float s0 = fmaf(sc[nt][r * 2 + 0], SCALE2, mk.x);
                    float s1 = fmaf(sc[nt][r * 2 + 1], SCALE2, mk.y);
                    sc[nt][r * 2 + 0] = s0;
                    sc[nt][r * 2 + 1] = s1;
                    rmax = fmaxf(rmax, fmaxf(s0, s1));
                }
            } else {
                const int ig = i0 + m0 + rg + r * 8;
#pragma unroll
                for (int nt = 0; nt < 8; nt++) {
                    const float2 mk = *(const float2*)&smask[buf][nt * 8 + tg * 2];
#pragma unroll
                    for (int e = 0; e < 2; e++) {
                        const int jg = j0 + nt * 8 + tg * 2 + e;
                        float s = fmaf(sc[nt][r * 2 + e], SCALE2, (e == 0) ? mk.x : mk.y);
                        if (jg - ig > (WIN - 1)) s = -1e30f;
                        sc[nt][r * 2 + e] = s;
                        rmax = fmaxf(rmax, s);
                    }
                }
            }
            rmax = fmaxf(rmax, __shfl_xor_sync(0xffffffffu, rmax, 1));
            rmax = fmaxf(rmax, __shfl_xor_sync(0xffffffffu, rmax, 2));
            const float mnew = fmaxf(mrow[r], rmax);
            const float alpha = ex2(mrow[r] - mnew);
            float rsum = 0.0f;
#pragma unroll
            for (int nt = 0; nt < 8; nt++)
#pragma unroll
                for (int e = 0; e < 2; e++) {
                    const float p = ex2(sc[nt][r * 2 + e] - mnew);
                    sc[nt][r * 2 + e] = p;
                    rsum += p;
                }
            rsum += __shfl_xor_sync(0xffffffffu, rsum, 1);
            rsum += __shfl_xor_sync(0xffffffffu, rsum, 2);
            lrow[r] = lrow[r] * alpha + rsum;
            mrow[r] = mnew;
#pragma unroll
            for (int nt = 0; nt < 8; nt++) {
                o[nt][r * 2 + 0] *= alpha;
                o[nt][r * 2 + 1] *= alpha;
            }
        }

#pragma unroll
        for (int u = 0; u < 4; u++) {
            uint32_t ph[4], pl[4];
            split_pack2(sc[2 * u][0],     sc[2 * u][1],     ph[0], pl[0]);
            split_pack2(sc[2 * u][2],     sc[2 * u][3],     ph[1], pl[1]);
            split_pack2(sc[2 * u + 1][0], sc[2 * u + 1][1], ph[2], pl[2]);
            split_pack2(sc[2 * u + 1][2], sc[2 * u + 1][3], ph[3], pl[3]);
#pragma unroll
            for (int np = 0; np < 8; np += 2) {
                const uint32_t bd = (uint32_t)((u * 16 + (g4 & 1) * 8 + (lane & 7)) * KROW
                                               + (np + (g4 >> 1)) * 8) * 2;
                uint32_t th[4], tl[4];
                ldsm4t(th, svh + bd);
                ldsm4t(tl, svl + bd);
                mma16816(o[np], ph, &th[0]);
                mma16816(o[np], ph, &tl[0]);
                mma16816(o[np], pl, &th[0]);
                mma16816(o[np + 1], ph, &th[2]);
                mma16816(o[np + 1], ph, &tl[2]);
                mma16816(o[np + 1], pl, &th[2]);
            }
        }
    }

#pragma unroll
    for (int r = 0; r < 2; r++) {
        const float inv = 1.0f / lrow[r];
        const int s_g = i0 + m0 + rg + r * 8;
        const size_t rowoff = ((size_t)b * NS + s_g) * D_MODEL + h * DH;
#pragma unroll
        for (int nt = 0; nt < 8; nt++) {
            uint32_t hi, lo;
            split_pack2(o[nt][r * 2] * inv, o[nt][r * 2 + 1] * inv, hi, lo);
            const size_t off = rowoff + nt * 8 + tg * 2;
            *(uint32_t*)(g_Chi + off) = hi;
            *(uint32_t*)(g_Clo + off) = lo;
        }
    }
}

// ---------------- host launcher ----------------
extern "C" void kernel_launch(void* const* d_in, const int* in_sizes, int n_in,
                              void* d_out, int out_size)
{
    const float* hidden = (const float*)d_in[0];
    const int* amask    = (const int*)d_in[1];
    const float* Wq     = (const float*)d_in[2];
    const float* Wk     = (const float*)d_in[3];
    const float* Wv     = (const float*)d_in[4];
    const float* Wo     = (const float*)d_in[5];
    float* out = (float*)d_out;

    static int attr_set = 0;
    if (!attr_set) {
        cudaFuncSetAttribute(gemm_mma, cudaFuncAttributeMaxDynamicSharedMemorySize, GEMM_SMEM);
        cudaFuncSetAttribute(attn_mma, cudaFuncAttributeMaxDynamicSharedMemorySize, ATTN_SMEM);
        attr_set = 1;
    }

    bf16 *pAhi, *pAlo, *pChi, *pClo;
    cudaGetSymbolAddress((void**)&pAhi, g_Ahi);
    cudaGetSymbolAddress((void**)&pAlo, g_Alo);
    cudaGetSymbolAddress((void**)&pChi, g_Chi);
    cudaGetSymbolAddress((void**)&pClo, g_Clo);

    // one pad: profiler captures the 4th launch -> attn_mma
    nop_pad<<<1, 32>>>();

    // 1. f32 -> bf16 hi/lo (X + stacked weights)
    convert_all<<<2 * (MROWS * D_MODEL / 4) / 256, 256>>>(hidden, Wq, Wk, Wv, Wo);

    // 2. fused QKV projection (N = 3072), scatter bf16 Q/K/V
    gemm_mma<<<dim3(3 * D_MODEL / 128, MROWS / 128), 128, GEMM_SMEM>>>(pAhi, pAlo, 0, 0, nullptr);

    // 3. attention
    attn_mma<<<dim3(NS / 64, NHEAD, NB), 128, ATTN_SMEM>>>(amask);

    // 4. output projection (weight rows 3072..4095), f32 out
    gemm_mma<<<dim3(D_MODEL / 128, MROWS / 128), 128, GEMM_SMEM>>>(pChi, pClo, 3 * D_MODEL, 1, out);
}

// round 8
// speedup vs baseline: 1.1272x; 1.1025x over previous
#include <cuda_runtime.h>
#include <cuda_bf16.h>
#include <cstdint>

#define D_MODEL 1024
#define NHEAD 16
#define DH 64
#define WIN 256
#define NB 2
#define NS 2048
#define MROWS (NB * NS)   // 4096

typedef __nv_bfloat16 bf16;

// 0.125 (1/sqrt(64)) * log2(e) — softmax computed in base-2 domain
#define SCALE2 0.1803368801111204f

// Swizzle<3,4,3> for 128-byte rows: XOR bits [6:4] with row bits [2:0]
#define SW(o) ((uint32_t)(o) ^ (((uint32_t)(o) >> 3) & 0x70u))

// ---------------- device scratch (allocation-free rule) ----------------
__device__ bf16 g_Ahi[MROWS * D_MODEL];
__device__ bf16 g_Alo[MROWS * D_MODEL];
__device__ bf16 g_Whi[4096 * D_MODEL];     // [Wq;Wk;Wv;Wo]
__device__ bf16 g_Wlo[4096 * D_MODEL];
__device__ bf16 g_Qhi[MROWS * D_MODEL];    // [b,h,s,d]
__device__ bf16 g_Qlo[MROWS * D_MODEL];
__device__ bf16 g_Khi[MROWS * D_MODEL];
__device__ bf16 g_Klo[MROWS * D_MODEL];
__device__ bf16 g_Vhi[MROWS * D_MODEL];
__device__ bf16 g_Vlo[MROWS * D_MODEL];
__device__ bf16 g_Chi[MROWS * D_MODEL];    // attention ctx, [b,s,e]
__device__ bf16 g_Clo[MROWS * D_MODEL];

// ---------------- helpers (all baseline PTX, sm_80+) ----------------
__device__ __forceinline__ uint32_t smem_u32(const void* p) {
    uint32_t a;
    asm("{ .reg .u64 t; cvta.to.shared.u64 t, %1; cvt.u32.u64 %0, t; }" : "=r"(a) : "l"(p));
    return a;
}
__device__ __forceinline__ void cp16(uint32_t s, const void* g) {
    asm volatile("cp.async.cg.shared.global [%0], [%1], 16;" :: "r"(s), "l"(g));
}
#define CP_COMMIT() asm volatile("cp.async.commit_group;" ::: "memory")
#define CP_WAIT0()  asm volatile("cp.async.wait_group 0;" ::: "memory")

__device__ __forceinline__ void ldsm4(uint32_t* r, uint32_t a) {
    asm volatile("ldmatrix.sync.aligned.m8n8.x4.shared.b16 {%0,%1,%2,%3}, [%4];"
        : "=r"(r[0]), "=r"(r[1]), "=r"(r[2]), "=r"(r[3]) : "r"(a));
}
__device__ __forceinline__ void ldsm4t(uint32_t* r, uint32_t a) {
    asm volatile("ldmatrix.sync.aligned.m8n8.x4.trans.shared.b16 {%0,%1,%2,%3}, [%4];"
        : "=r"(r[0]), "=r"(r[1]), "=r"(r[2]), "=r"(r[3]) : "r"(a));
}
__device__ __forceinline__ void mma16816(float* c, const uint32_t* a, const uint32_t* b) {
    asm volatile("mma.sync.aligned.m16n8k16.row.col.f32.bf16.bf16.f32 "
        "{%0,%1,%2,%3}, {%4,%5,%6,%7}, {%8,%9}, {%0,%1,%2,%3};"
        : "+f"(c[0]), "+f"(c[1]), "+f"(c[2]), "+f"(c[3])
        : "r"(a[0]), "r"(a[1]), "r"(a[2]), "r"(a[3]), "r"(b[0]), "r"(b[1]));
}
__device__ __forceinline__ float ex2(float x) {
    float r;
    asm("ex2.approx.ftz.f32 %0, %1;" : "=f"(r) : "f"(x));
    return r;
}

// split two f32 into bf16x2 hi + bf16x2 lo (x0 in low half)
__device__ __forceinline__ void split_pack2(float x0, float x1, uint32_t& hi, uint32_t& lo) {
    __nv_bfloat162 h = __float22bfloat162_rn(make_float2(x0, x1));
    float h0 = __bfloat162float(h.x), h1 = __bfloat162float(h.y);
    __nv_bfloat162 l = __float22bfloat162_rn(make_float2(x0 - h0, x1 - h1));
    hi = *(uint32_t*)&h;
    lo = *(uint32_t*)&l;
}

// pad kernel: the profiler captures the 4th launch -> attn_mma
__global__ void nop_pad() {}

// ---------------- convert f32 -> bf16 hi/lo (X and stacked weights) ----------------
__global__ void __launch_bounds__(256) convert_all(const float* __restrict__ X,
                                                   const float* __restrict__ Wq,
                                                   const float* __restrict__ Wk,
                                                   const float* __restrict__ Wv,
                                                   const float* __restrict__ Wo)
{
    const size_t NA4 = (size_t)MROWS * D_MODEL / 4;
    size_t i4 = (size_t)blockIdx.x * blockDim.x + threadIdx.x;
    const float* src;
    bf16 *dh, *dl;
    size_t off;
    if (i4 < NA4) {
        off = i4 * 4;
        src = X + off;
        dh = g_Ahi; dl = g_Alo;
    } else {
        size_t j = (i4 - NA4) * 4;
        off = j;
        int row = (int)(j >> 10);
        int col = (int)(j & 1023);
        const float* W = (row < 1024) ? Wq : (row < 2048) ? Wk : (row < 3072) ? Wv : Wo;
        src = W + (size_t)(row & 1023) * D_MODEL + col;
        dh = g_Whi; dl = g_Wlo;
    }
    float4 v = *(const float4*)src;
    uint32_t h0, l0, h1, l1;
    split_pack2(v.x, v.y, h0, l0);
    split_pack2(v.z, v.w, h1, l1);
    *(uint2*)(dh + off) = make_uint2(h0, h1);
    *(uint2*)(dl + off) = make_uint2(l0, l1);
}

// ---------------- GEMM: 128x128 CTA, 4 warps, warp 64x64, loads issued mid-kt ----------------
#define SROW 40                 // 32 + 8 pad (bf16 elems per smem row)
#define MAT_ELEMS (128 * SROW)  // 5120
#define STAGE_ELEMS (4 * MAT_ELEMS)
#define GEMM_SMEM (2 * STAGE_ELEMS * 2)  // 81920 B

__global__ void __launch_bounds__(128) gemm_mma(const bf16* __restrict__ Ahi,
                                                const bf16* __restrict__ Alo,
                                                int wrow0, int mode,
                                                float* __restrict__ out)
{
    extern __shared__ bf16 sm[];
    const int tid = threadIdx.x, lane = tid & 31, wid = tid >> 5;
    const int bm = blockIdx.y * 128, bn = blockIdx.x * 128;
    const bf16* Whi = g_Whi + (size_t)wrow0 * D_MODEL;
    const bf16* Wlo = g_Wlo + (size_t)wrow0 * D_MODEL;
    const uint32_t sbase = smem_u32(sm);

    float acc[4][8][4];
#pragma unroll
    for (int i = 0; i < 4; i++)
#pragma unroll
        for (int j = 0; j < 8; j++)
#pragma unroll
            for (int k = 0; k < 4; k++) acc[i][j][k] = 0.0f;

    const int wm = (wid & 1) * 64, wn = (wid >> 1) * 64;
    const int tg = lane & 3, rg = lane >> 2;
    const int g4 = lane >> 3;

    auto load_stage = [&](int k0, int bufs) {
        const uint32_t st = sbase + (uint32_t)(bufs * STAGE_ELEMS) * 2;
#pragma unroll
        for (int i = 0; i < 16; i++) {
            int c = tid + i * 128;
            int mat = c >> 9;
            int idx = c & 511;
            int row = idx >> 2, cc = idx & 3;
            const bf16* src = (mat == 0) ? Ahi : (mat == 1) ? Alo : (mat == 2) ? Whi : Wlo;
            const int row0 = (mat < 2) ? bm : bn;
            cp16(st + (uint32_t)(mat * MAT_ELEMS + row * SROW + cc * 8) * 2,
                 src + (size_t)(row0 + row) * D_MODEL + k0 + cc * 8);
        }
    };

    // one kk (K=16) slice of compute on stage sA
    auto compute_kk = [&](uint32_t sA, int kk) {
        uint32_t ah[4][4], al[4][4];
#pragma unroll
        for (int mi = 0; mi < 4; mi++) {
            uint32_t ad = sA + (uint32_t)((wm + mi * 16 + (lane & 15)) * SROW + kk + (lane >> 4) * 8) * 2;
            ldsm4(ah[mi], ad);
            ldsm4(al[mi], ad + MAT_ELEMS * 2);
        }
#pragma unroll
        for (int nh = 0; nh < 2; nh++) {
            uint32_t bh[4][2], bl[4][2];
#pragma unroll
            for (int np = 0; np < 4; np += 2) {
                uint32_t bd = sA + (uint32_t)(2 * MAT_ELEMS +
                    (wn + nh * 32 + (np + (g4 >> 1)) * 8 + (lane & 7)) * SROW + kk + (g4 & 1) * 8) * 2;
                uint32_t t[4];
                ldsm4(t, bd);
                bh[np][0] = t[0]; bh[np][1] = t[1]; bh[np + 1][0] = t[2]; bh[np + 1][1] = t[3];
                ldsm4(t, bd + MAT_ELEMS * 2);
                bl[np][0] = t[0]; bl[np][1] = t[1]; bl[np + 1][0] = t[2]; bl[np + 1][1] = t[3];
            }
#pragma unroll
            for (int mi = 0; mi < 4; mi++)
#pragma unroll
                for (int ni = 0; ni < 4; ni++) {
                    float* a2 = acc[mi][nh * 4 + ni];
                    mma16816(a2, ah[mi], bh[ni]);
                    mma16816(a2, ah[mi], bl[ni]);
                    mma16816(a2, al[mi], bh[ni]);
                }
        }
    };

    load_stage(0, 0);
    CP_COMMIT();

    for (int kt = 0; kt < 32; kt++) {
        const int buf = kt & 1;
        CP_WAIT0();
        __syncthreads();
        const uint32_t sA = sbase + (uint32_t)(buf * STAGE_ELEMS) * 2;
        compute_kk(sA, 0);                 // LDSMs reach the LSU before the LDGSTS burst
        if (kt + 1 < 32) {
            load_stage((kt + 1) * 32, buf ^ 1);
            CP_COMMIT();
        }
        compute_kk(sA, 16);
    }

    // epilogue
#pragma unroll
    for (int mi = 0; mi < 4; mi++) {
        const int mrow0 = bm + wm + mi * 16 + rg;
#pragma unroll
        for (int ni = 0; ni < 8; ni++) {
            const int ngl = bn + wn + ni * 8 + tg * 2;
#pragma unroll
            for (int r = 0; r < 2; r++) {
                const int m = mrow0 + r * 8;
                const float x0 = acc[mi][ni][r * 2], x1 = acc[mi][ni][r * 2 + 1];
                if (mode == 0) {
                    const int mat = ngl >> 10, e = ngl & 1023, hh = e >> 6, dd = e & 63;
                    const int bb = m >> 11, ss = m & (NS - 1);
                    const size_t off = ((size_t)(bb * NHEAD + hh) * NS + ss) * DH + dd;
                    uint32_t hi, lo;
                    split_pack2(x0, x1, hi, lo);
                    bf16 *ph, *pl;
                    if (mat == 0)      { ph = g_Qhi; pl = g_Qlo; }
                    else if (mat == 1) { ph = g_Khi; pl = g_Klo; }
                    else               { ph = g_Vhi; pl = g_Vlo; }
                    *(uint32_t*)(ph + off) = hi;
                    *(uint32_t*)(pl + off) = lo;
                } else {
                    *(float2*)(out + (size_t)m * D_MODEL + ngl) = make_float2(x0, x1);
                }
            }
        }
    }
}

// ---------------- attention v5: swizzled smem (no pad) -> 3 CTAs/SM ----------------
// stage = 4 mats (Khi,Klo,Vhi,Vlo) x 64 rows x 128B = 32768 B
#define AMAT_B 8192
#define ASTAGE_B (4 * AMAT_B)           // 32768
#define ATTN_SMEM (2 * ASTAGE_B)        // 65536

__global__ void __launch_bounds__(128) attn_mma(const int* __restrict__ amask)
{
    extern __shared__ char dynsm[];
    __shared__ float smask[2][64];

    const int tid = threadIdx.x, lane = tid & 31, wid = tid >> 5;
    const int tg = lane & 3, rg = lane >> 2;
    const int i0 = (gridDim.x - 1 - blockIdx.x) * 64;    // longest-first
    const int h = blockIdx.y, b = blockIdx.z;
    const size_t base = ((size_t)(b * NHEAD + h)) * NS * DH;
    const uint32_t sbase = smem_u32(dynsm);

    // ---- stage Q (64x64 hi/lo) through stage-0 mats 0/1, ldmatrix to regs ----
#pragma unroll
    for (int i = 0; i < 4; i++) {
        int c = tid + i * 128;              // 0..511 = 64 rows x 8 16B-chunks
        int row = c >> 3, cc = c & 7;
        const size_t g = base + (size_t)(i0 + row) * DH + cc * 8;
        const uint32_t so = SW(row * 128 + cc * 16);
        cp16(sbase + so, g_Qhi + g);
        cp16(sbase + AMAT_B + so, g_Qlo + g);
    }
    CP_COMMIT();
    CP_WAIT0();
    __syncthreads();

    const int m0 = wid * 16;
    uint32_t qh[4][4], ql[4][4];
#pragma unroll
    for (int u = 0; u < 4; u++) {
        const uint32_t off = SW((m0 + (lane & 15)) * 128 + u * 32 + (lane >> 4) * 16);
        ldsm4(qh[u], sbase + off);
        ldsm4(ql[u], sbase + AMAT_B + off);
    }
    __syncthreads();   // all warps done reading Q before stage-0 K/V overwrite

    float o[8][4];
#pragma unroll
    for (int i = 0; i < 8; i++)
#pragma unroll
        for (int j = 0; j < 4; j++) o[i][j] = 0.0f;
    float mrow[2] = {-1e30f, -1e30f}, lrow[2] = {0.0f, 0.0f};

    const int jlast = min(i0 + 63 + (WIN - 1), NS - 1) >> 6;

    auto load_stage = [&](int j0, int bufs) {
        const uint32_t st = sbase + (uint32_t)bufs * ASTAGE_B;
#pragma unroll
        for (int i = 0; i < 16; i++) {
            int c = tid + i * 128;           // 0..2047 = 4 mats x 64 rows x 8 chunks
            int mat = c >> 9;
            int idx = c & 511;
            int row = idx >> 3, cc = idx & 7;
            const size_t g = base + (size_t)(j0 + row) * DH + cc * 8;
            const bf16* src = (mat == 0) ? g_Khi : (mat == 1) ? g_Klo
                            : (mat == 2) ? g_Vhi : g_Vlo;
            cp16(st + (uint32_t)mat * AMAT_B + SW(row * 128 + cc * 16), src + g);
        }
        if (tid < 64)
            smask[bufs][tid] = (amask[b * NS + j0 + tid] != 0) ? 0.0f : -1e30f;
    };

    load_stage(0, 0);
    CP_COMMIT();

    for (int t = 0; t <= jlast; t++) {
        const int buf = t & 1;
        CP_WAIT0();
        __syncthreads();

        const uint32_t st = sbase + (uint32_t)buf * ASTAGE_B;
        const int j0 = t * 64;
        const int g4 = lane >> 3;

        // ---- S = Q K^T ----
        float sc[8][4];
#pragma unroll
        for (int i = 0; i < 8; i++)
#pragma unroll
            for (int j = 0; j < 4; j++) sc[i][j] = 0.0f;

#pragma unroll
        for (int u = 0; u < 4; u++) {
#pragma unroll
            for (int np = 0; np < 8; np += 2) {
                const uint32_t bd = SW(((np + (g4 >> 1)) * 8 + (lane & 7)) * 128
                                       + u * 32 + (g4 & 1) * 16);
                uint32_t th[4], tl[4];
                ldsm4(th, st + bd);
                ldsm4(tl, st + AMAT_B + bd);
                mma16816(sc[np], qh[u], &th[0]);
                mma16816(sc[np], qh[u], &tl[0]);
                mma16816(sc[np], ql[u], &th[0]);
                mma16816(sc[np + 1], qh[u], &th[2]);
                mma16816(sc[np + 1], qh[u], &tl[2]);
                mma16816(sc[np + 1], ql[u], &th[2]);
            }
        }

        // issue next tile's loads now — the LDGSTS burst overlaps softmax + PV
        if (t < jlast) {
            load_stage((t + 1) * 64, buf ^ 1);
            CP_COMMIT();
        }

        // ---- mask + scale (base-2 domain) + online softmax ----
        const bool interior = (j0 <= i0 + m0 + (WIN - 1) - 63);

#pragma unroll
        for (int r = 0; r < 2; r++) {
            float rmax = -1e30f;
            if (interior) {
#pragma unroll
                for (int nt = 0; nt < 8; nt++) {
                    const float2 mk = *(const float2*)&smask[buf][nt * 8 + tg * 2];
                    float s0 = fmaf(sc[nt][r * 2 + 0], SCALE2, mk.x);
                    float s1 = fmaf(sc[nt][r * 2 + 1], SCALE2, mk.y);
                    sc[nt][r * 2 + 0] = s0;
                    sc[nt][r * 2 + 1] = s1;
                    rmax = fmaxf(rmax, fmaxf(s0, s1));
                }
            } else {
                const int ig = i0 + m0 + rg + r * 8;
#pragma unroll
                for (int nt = 0; nt < 8; nt++) {
                    const float2 mk = *(const float2*)&smask[buf][nt * 8 + tg * 2];
#pragma unroll
                    for (int e = 0; e < 2; e++) {
                        const int jg = j0 + nt * 8 + tg * 2 + e;
                        float s = fmaf(sc[nt][r * 2 + e], SCALE2, (e == 0) ? mk.x : mk.y);
                        if (jg - ig > (WIN - 1)) s = -1e30f;
                        sc[nt][r * 2 + e] = s;
                        rmax = fmaxf(rmax, s);
                    }
                }
            }
            rmax = fmaxf(rmax, __shfl_xor_sync(0xffffffffu, rmax, 1));
            rmax = fmaxf(rmax, __shfl_xor_sync(0xffffffffu, rmax, 2));
            const float mnew = fmaxf(mrow[r], rmax);
            const float alpha = ex2(mrow[r] - mnew);
            float rsum = 0.0f;
#pragma unroll
            for (int nt = 0; nt < 8; nt++)
#pragma unroll
                for (int e = 0; e < 2; e++) {
                    const float p = ex2(sc[nt][r * 2 + e] - mnew);
                    sc[nt][r * 2 + e] = p;
                    rsum += p;
                }
            rsum += __shfl_xor_sync(0xffffffffu, rsum, 1);
            rsum += __shfl_xor_sync(0xffffffffu, rsum, 2);
            lrow[r] = lrow[r] * alpha + rsum;
            mrow[r] = mnew;
#pragma unroll
            for (int nt = 0; nt < 8; nt++) {
                o[nt][r * 2 + 0] *= alpha;
                o[nt][r * 2 + 1] *= alpha;
            }
        }

        // ---- O += P V  (P split computed per-u to cap register pressure) ----
#pragma unroll
        for (int u = 0; u < 4; u++) {
            uint32_t ph[4], pl[4];
            split_pack2(sc[2 * u][0],     sc[2 * u][1],     ph[0], pl[0]);
            split_pack2(sc[2 * u][2],     sc[2 * u][3],     ph[1], pl[1]);
            split_pack2(sc[2 * u + 1][0], sc[2 * u + 1][1], ph[2], pl[2]);
            split_pack2(sc[2 * u + 1][2], sc[2 * u + 1][3], ph[3], pl[3]);
#pragma unroll
            for (int np = 0; np < 8; np += 2) {
                const uint32_t bd = SW((u * 16 + (g4 & 1) * 8 + (lane & 7)) * 128
                                       + (np + (g4 >> 1)) * 16);
                uint32_t th[4], tl[4];
                ldsm4t(th, st + 2 * AMAT_B + bd);
                ldsm4t(tl, st + 3 * AMAT_B + bd);
                mma16816(o[np], ph, &th[0]);
                mma16816(o[np], ph, &tl[0]);
                mma16816(o[np], pl, &th[0]);
                mma16816(o[np + 1], ph, &th[2]);
                mma16816(o[np + 1], ph, &tl[2]);
                mma16816(o[np + 1], pl, &th[2]);
            }
        }
    }

    // ---- epilogue: ctx as bf16 hi/lo [b,s,e] ----
#pragma unroll
    for (int r = 0; r < 2; r++) {
        const float inv = 1.0f / lrow[r];
        const int s_g = i0 + m0 + rg + r * 8;
        const size_t rowoff = ((size_t)b * NS + s_g) * D_MODEL + h * DH;
#pragma unroll
        for (int nt = 0; nt < 8; nt++) {
            uint32_t hi, lo;
            split_pack2(o[nt][r * 2] * inv, o[nt][r * 2 + 1] * inv, hi, lo);
            const size_t off = rowoff + nt * 8 + tg * 2;
            *(uint32_t*)(g_Chi + off) = hi;
            *(uint32_t*)(g_Clo + off) = lo;
        }
    }
}

// ---------------- host launcher ----------------
extern "C" void kernel_launch(void* const* d_in, const int* in_sizes, int n_in,
                              void* d_out, int out_size)
{
    const float* hidden = (const float*)d_in[0];
    const int* amask    = (const int*)d_in[1];
    const float* Wq     = (const float*)d_in[2];
    const float* Wk     = (const float*)d_in[3];
    const float* Wv     = (const float*)d_in[4];
    const float* Wo     = (const float*)d_in[5];
    float* out = (float*)d_out;

    static int attr_set = 0;
    if (!attr_set) {
        cudaFuncSetAttribute(gemm_mma, cudaFuncAttributeMaxDynamicSharedMemorySize, GEMM_SMEM);
        cudaFuncSetAttribute(attn_mma, cudaFuncAttributeMaxDynamicSharedMemorySize, ATTN_SMEM);
        cudaFuncSetAttribute(attn_mma, cudaFuncAttributePreferredSharedMemoryCarveout, 100);
        cudaFuncSetAttribute(gemm_mma, cudaFuncAttributePreferredSharedMemoryCarveout, 100);
        attr_set = 1;
    }

    bf16 *pAhi, *pAlo, *pChi, *pClo;
    cudaGetSymbolAddress((void**)&pAhi, g_Ahi);
    cudaGetSymbolAddress((void**)&pAlo, g_Alo);
    cudaGetSymbolAddress((void**)&pChi, g_Chi);
    cudaGetSymbolAddress((void**)&pClo, g_Clo);

    // one pad: profiler captures the 4th launch -> attn_mma
    nop_pad<<<1, 32>>>();

    // 1. f32 -> bf16 hi/lo (X + stacked weights)
    convert_all<<<2 * (MROWS * D_MODEL / 4) / 256, 256>>>(hidden, Wq, Wk, Wv, Wo);

    // 2. fused QKV projection (N = 3072), scatter bf16 Q/K/V
    gemm_mma<<<dim3(3 * D_MODEL / 128, MROWS / 128), 128, GEMM_SMEM>>>(pAhi, pAlo, 0, 0, nullptr);

    // 3. attention (swizzled, 3 CTAs/SM target)
    attn_mma<<<dim3(NS / 64, NHEAD, NB), 128, ATTN_SMEM>>>(amask);

    // 4. output projection (weight rows 3072..4095), f32 out
    gemm_mma<<<dim3(D_MODEL / 128, MROWS / 128), 128, GEMM_SMEM>>>(pChi, pClo, 3 * D_MODEL, 1, out);
}

// round 9
// speedup vs baseline: 1.4551x; 1.2909x over previous
#include <cuda_runtime.h>
#include <cuda_fp16.h>
#include <cstdint>

#define D_MODEL 1024
#define NHEAD 16
#define DH 64
#define WIN 256
#define NB 2
#define NS 2048
#define MROWS (NB * NS)   // 4096

// 0.125 (1/sqrt(64)) * log2(e) — softmax computed in base-2 domain
#define SCALE2 0.1803368801111204f

// Swizzle<3,4,3> for 128-byte rows
#define SW(o) ((uint32_t)(o) ^ (((uint32_t)(o) >> 3) & 0x70u))

// ---------------- device scratch (allocation-free rule) ----------------
__device__ __half g_Ah[MROWS * D_MODEL];
__device__ __half g_Al[MROWS * D_MODEL];
__device__ __half g_Wh[4096 * D_MODEL];     // fp16([Wq;Wk;Wv;Wo])
__device__ __half g_Qh[MROWS * D_MODEL];    // [b,h,s,d] Q split hi
__device__ __half g_Ql[MROWS * D_MODEL];    // Q split lo
__device__ __half g_Kh[MROWS * D_MODEL];    // K rounded
__device__ __half g_Vh[MROWS * D_MODEL];    // V rounded
__device__ __half g_Ch[MROWS * D_MODEL];    // ctx split hi, [b,s,e]
__device__ __half g_Cl[MROWS * D_MODEL];    // ctx split lo

// ---------------- helpers ----------------
__device__ __forceinline__ uint32_t smem_u32(const void* p) {
    uint32_t a;
    asm("{ .reg .u64 t; cvta.to.shared.u64 t, %1; cvt.u32.u64 %0, t; }" : "=r"(a) : "l"(p));
    return a;
}
__device__ __forceinline__ void cp16(uint32_t s, const void* g) {
    asm volatile("cp.async.cg.shared.global [%0], [%1], 16;" :: "r"(s), "l"(g));
}
#define CP_COMMIT() asm volatile("cp.async.commit_group;" ::: "memory")
#define CP_WAIT0()  asm volatile("cp.async.wait_group 0;" ::: "memory")

__device__ __forceinline__ void ldsm4(uint32_t* r, uint32_t a) {
    asm volatile("ldmatrix.sync.aligned.m8n8.x4.shared.b16 {%0,%1,%2,%3}, [%4];"
        : "=r"(r[0]), "=r"(r[1]), "=r"(r[2]), "=r"(r[3]) : "r"(a));
}
__device__ __forceinline__ void ldsm4t(uint32_t* r, uint32_t a) {
    asm volatile("ldmatrix.sync.aligned.m8n8.x4.trans.shared.b16 {%0,%1,%2,%3}, [%4];"
        : "=r"(r[0]), "=r"(r[1]), "=r"(r[2]), "=r"(r[3]) : "r"(a));
}
__device__ __forceinline__ void mma16816(float* c, const uint32_t* a, const uint32_t* b) {
    asm volatile("mma.sync.aligned.m16n8k16.row.col.f32.f16.f16.f32 "
        "{%0,%1,%2,%3}, {%4,%5,%6,%7}, {%8,%9}, {%0,%1,%2,%3};"
        : "+f"(c[0]), "+f"(c[1]), "+f"(c[2]), "+f"(c[3])
        : "r"(a[0]), "r"(a[1]), "r"(a[2]), "r"(a[3]), "r"(b[0]), "r"(b[1]));
}
__device__ __forceinline__ float ex2(float x) {
    float r;
    asm("ex2.approx.ftz.f32 %0, %1;" : "=f"(r) : "f"(x));
    return r;
}

// two f32 -> fp16x2 hi + fp16x2 lo (2-term split)
__device__ __forceinline__ void split2h(float x0, float x1, uint32_t& hi, uint32_t& lo) {
    __half2 h = __float22half2_rn(make_float2(x0, x1));
    float h0 = __low2float(h), h1 = __high2float(h);
    __half2 l = __float22half2_rn(make_float2(x0 - h0, x1 - h1));
    hi = *(uint32_t*)&h;
    lo = *(uint32_t*)&l;
}
// two f32 -> fp16x2 (round only)
__device__ __forceinline__ uint32_t round2h(float x0, float x1) {
    __half2 h = __float22half2_rn(make_float2(x0, x1));
    return *(uint32_t*)&h;
}

// pad kernel: the profiler captures the 4th launch -> attn_mma
__global__ void nop_pad() {}

// ---------------- convert: X -> Ah+Al (split), W -> Wh (round) ----------------
__global__ void __launch_bounds__(256) convert_all(const float* __restrict__ X,
                                                   const float* __restrict__ Wq,
                                                   const float* __restrict__ Wk,
                                                   const float* __restrict__ Wv,
                                                   const float* __restrict__ Wo)
{
    const size_t NA4 = (size_t)MROWS * D_MODEL / 4;
    size_t i4 = (size_t)blockIdx.x * blockDim.x + threadIdx.x;
    if (i4 < NA4) {
        const size_t off = i4 * 4;
        float4 v = *(const float4*)(X + off);
        uint32_t h0, l0, h1, l1;
        split2h(v.x, v.y, h0, l0);
        split2h(v.z, v.w, h1, l1);
        *(uint2*)(g_Ah + off) = make_uint2(h0, h1);
        *(uint2*)(g_Al + off) = make_uint2(l0, l1);
    } else {
        const size_t j = (i4 - NA4) * 4;
        const int row = (int)(j >> 10);
        const int col = (int)(j & 1023);
        const float* W = (row < 1024) ? Wq : (row < 2048) ? Wk : (row < 3072) ? Wv : Wo;
        float4 v = *(const float4*)(W + (size_t)(row & 1023) * D_MODEL + col);
        *(uint2*)(g_Wh + j) = make_uint2(round2h(v.x, v.y), round2h(v.z, v.w));
    }
}

// ---------------- GEMM: 128x128 CTA, 4 warps (64x64 each), 2-pass fp16 split ----------------
// C[m,n] = sum_k A[m,k]*W[n,k] with A = Ah+Al (fp16), W = Wh (fp16 rounded).
#define SROW 40                 // 32 + 8 pad (fp16 elems per smem row)
#define MAT_ELEMS (128 * SROW)  // 5120
#define STAGE_ELEMS (3 * MAT_ELEMS)      // Ah, Al, Wh
#define GEMM_SMEM (2 * STAGE_ELEMS * 2)  // 61440 B

__global__ void __launch_bounds__(128) gemm_mma(const __half* __restrict__ Ahp,
                                                const __half* __restrict__ Alp,
                                                int wrow0, int mode,
                                                float* __restrict__ out)
{
    extern __shared__ __half sm[];
    const int tid = threadIdx.x, lane = tid & 31, wid = tid >> 5;
    const int bm = blockIdx.y * 128, bn = blockIdx.x * 128;
    const __half* Whp = g_Wh + (size_t)wrow0 * D_MODEL;
    const uint32_t sbase = smem_u32(sm);

    float acc[4][8][4];
#pragma unroll
    for (int i = 0; i < 4; i++)
#pragma unroll
        for (int j = 0; j < 8; j++)
#pragma unroll
            for (int k = 0; k < 4; k++) acc[i][j][k] = 0.0f;

    const int wm = (wid & 1) * 64, wn = (wid >> 1) * 64;
    const int tg = lane & 3, rg = lane >> 2;
    const int g4 = lane >> 3;

    // 3 mats x 128 rows x 4 16B-chunks = 1536 cp16 / 128 threads = 12 iters
    auto load_stage = [&](int k0, int bufs) {
        const uint32_t st = sbase + (uint32_t)(bufs * STAGE_ELEMS) * 2;
#pragma unroll
        for (int i = 0; i < 12; i++) {
            int c = tid + i * 128;
            int mat = c >> 9;
            int idx = c & 511;
            int row = idx >> 2, cc = idx & 3;
            const __half* src = (mat == 0) ? Ahp : (mat == 1) ? Alp : Whp;
            const int row0 = (mat < 2) ? bm : bn;
            cp16(st + (uint32_t)(mat * MAT_ELEMS + row * SROW + cc * 8) * 2,
                 src + (size_t)(row0 + row) * D_MODEL + k0 + cc * 8);
        }
    };

    auto compute_kk = [&](uint32_t sA, int kk) {
        uint32_t ah[4][4], al[4][4];
#pragma unroll
        for (int mi = 0; mi < 4; mi++) {
            uint32_t ad = sA + (uint32_t)((wm + mi * 16 + (lane & 15)) * SROW + kk + (lane >> 4) * 8) * 2;
            ldsm4(ah[mi], ad);
            ldsm4(al[mi], ad + MAT_ELEMS * 2);
        }
#pragma unroll
        for (int nh = 0; nh < 2; nh++) {
            uint32_t bh[4][2];
#pragma unroll
            for (int np = 0; np < 4; np += 2) {
                uint32_t bd = sA + (uint32_t)(2 * MAT_ELEMS +
                    (wn + nh * 32 + (np + (g4 >> 1)) * 8 + (lane & 7)) * SROW + kk + (g4 & 1) * 8) * 2;
                uint32_t t[4];
                ldsm4(t, bd);
                bh[np][0] = t[0]; bh[np][1] = t[1]; bh[np + 1][0] = t[2]; bh[np + 1][1] = t[3];
            }
#pragma unroll
            for (int mi = 0; mi < 4; mi++)
#pragma unroll
                for (int ni = 0; ni < 4; ni++) {
                    float* a2 = acc[mi][nh * 4 + ni];
                    mma16816(a2, ah[mi], bh[ni]);
                    mma16816(a2, al[mi], bh[ni]);
                }
        }
    };

    load_stage(0, 0);
    CP_COMMIT();

    for (int kt = 0; kt < 32; kt++) {
        const int buf = kt & 1;
        CP_WAIT0();
        __syncthreads();
        const uint32_t sA = sbase + (uint32_t)(buf * STAGE_ELEMS) * 2;
        compute_kk(sA, 0);
        if (kt + 1 < 32) {
            load_stage((kt + 1) * 32, buf ^ 1);
            CP_COMMIT();
        }
        compute_kk(sA, 16);
    }

    // epilogue
#pragma unroll
    for (int mi = 0; mi < 4; mi++) {
        const int mrow0 = bm + wm + mi * 16 + rg;
#pragma unroll
        for (int ni = 0; ni < 8; ni++) {
            const int ngl = bn + wn + ni * 8 + tg * 2;
#pragma unroll
            for (int r = 0; r < 2; r++) {
                const int m = mrow0 + r * 8;
                const float x0 = acc[mi][ni][r * 2], x1 = acc[mi][ni][r * 2 + 1];
                if (mode == 0) {
                    const int mat = ngl >> 10, e = ngl & 1023, hh = e >> 6, dd = e & 63;
                    const int bb = m >> 11, ss = m & (NS - 1);
                    const size_t off = ((size_t)(bb * NHEAD + hh) * NS + ss) * DH + dd;
                    if (mat == 0) {                 // Q: 2-term split
                        uint32_t hi, lo;
                        split2h(x0, x1, hi, lo);
                        *(uint32_t*)(g_Qh + off) = hi;
                        *(uint32_t*)(g_Ql + off) = lo;
                    } else if (mat == 1) {          // K: round
                        *(uint32_t*)(g_Kh + off) = round2h(x0, x1);
                    } else {                        // V: round
                        *(uint32_t*)(g_Vh + off) = round2h(x0, x1);
                    }
                } else {
                    *(float2*)(out + (size_t)m * D_MODEL + ngl) = make_float2(x0, x1);
                }
            }
        }
    }
}

// ---------------- attention v6: fp16 2-pass, K/V single (16KB/stage) ----------------
#define AMAT_B 8192                      // 64 rows x 128 B
#define ASTAGE_B (2 * AMAT_B)            // Kh + Vh = 16384
#define ATTN_SMEM (2 * ASTAGE_B)         // 32768 dynamic

__global__ void __launch_bounds__(128, 3) attn_mma(const int* __restrict__ amask)
{
    extern __shared__ char dynsm[];
    __shared__ float smask[2][64];

    const int tid = threadIdx.x, lane = tid & 31, wid = tid >> 5;
    const int tg = lane & 3, rg = lane >> 2;
    const int i0 = (gridDim.x - 1 - blockIdx.x) * 64;    // longest-first
    const int h = blockIdx.y, b = blockIdx.z;
    const size_t base = ((size_t)(b * NHEAD + h)) * NS * DH;
    const uint32_t sbase = smem_u32(dynsm);

    // ---- stage Q (64x64 hi/lo) through stage-0 slots, ldmatrix to regs ----
#pragma unroll
    for (int i = 0; i < 4; i++) {
        int c = tid + i * 128;              // 64 rows x 8 chunks
        int row = c >> 3, cc = c & 7;
        const size_t g = base + (size_t)(i0 + row) * DH + cc * 8;
        const uint32_t so = SW(row * 128 + cc * 16);
        cp16(sbase + so, g_Qh + g);
        cp16(sbase + AMAT_B + so, g_Ql + g);
    }
    CP_COMMIT();
    CP_WAIT0();
    __syncthreads();

    const int m0 = wid * 16;
    uint32_t qh[4][4], ql[4][4];
#pragma unroll
    for (int u = 0; u < 4; u++) {
        const uint32_t off = SW((m0 + (lane & 15)) * 128 + u * 32 + (lane >> 4) * 16);
        ldsm4(qh[u], sbase + off);
        ldsm4(ql[u], sbase + AMAT_B + off);
    }
    __syncthreads();

    float o[8][4];
#pragma unroll
    for (int i = 0; i < 8; i++)
#pragma unroll
        for (int j = 0; j < 4; j++) o[i][j] = 0.0f;
    float mrow[2] = {-1e30f, -1e30f}, lrow[2] = {0.0f, 0.0f};

    const int jlast = min(i0 + 63 + (WIN - 1), NS - 1) >> 6;

    // 2 mats (Kh, Vh) x 64 rows x 8 chunks = 1024 cp16 / 128 thr = 8 iters
    auto load_stage = [&](int j0, int bufs) {
        const uint32_t st = sbase + (uint32_t)bufs * ASTAGE_B;
#pragma unroll
        for (int i = 0; i < 8; i++) {
            int c = tid + i * 128;
            int mat = c >> 9;
            int idx = c & 511;
            int row = idx >> 3, cc = idx & 7;
            const size_t g = base + (size_t)(j0 + row) * DH + cc * 8;
            const __half* src = (mat == 0) ? g_Kh : g_Vh;
            cp16(st + (uint32_t)mat * AMAT_B + SW(row * 128 + cc * 16), src + g);
        }
        if (tid < 64)
            smask[bufs][tid] = (amask[b * NS + j0 + tid] != 0) ? 0.0f : -1e30f;
    };

    load_stage(0, 0);
    CP_COMMIT();

    for (int t = 0; t <= jlast; t++) {
        const int buf = t & 1;
        CP_WAIT0();
        __syncthreads();

        const uint32_t st = sbase + (uint32_t)buf * ASTAGE_B;
        const int j0 = t * 64;
        const int g4 = lane >> 3;

        // ---- S = Q K^T (2-pass: qh·kh + ql·kh) ----
        float sc[8][4];
#pragma unroll
        for (int i = 0; i < 8; i++)
#pragma unroll
            for (int j = 0; j < 4; j++) sc[i][j] = 0.0f;

#pragma unroll
        for (int u = 0; u < 4; u++) {
#pragma unroll
            for (int np = 0; np < 8; np += 2) {
                const uint32_t bd = SW(((np + (g4 >> 1)) * 8 + (lane & 7)) * 128
                                       + u * 32 + (g4 & 1) * 16);
                uint32_t th[4];
                ldsm4(th, st + bd);
                mma16816(sc[np], qh[u], &th[0]);
                mma16816(sc[np], ql[u], &th[0]);
                mma16816(sc[np + 1], qh[u], &th[2]);
                mma16816(sc[np + 1], ql[u], &th[2]);
            }
        }

        // prefetch next tile under softmax + PV
        if (t < jlast) {
            load_stage((t + 1) * 64, buf ^ 1);
            CP_COMMIT();
        }

        // ---- mask + scale (base-2) + online softmax ----
        const bool interior = (j0 <= i0 + m0 + (WIN - 1) - 63);

#pragma unroll
        for (int r = 0; r < 2; r++) {
            float rmax = -1e30f;
            if (interior) {
#pragma unroll
                for (int nt = 0; nt < 8; nt++) {
                    const float2 mk = *(const float2*)&smask[buf][nt * 8 + tg * 2];
                    float s0 = fmaf(sc[nt][r * 2 + 0], SCALE2, mk.x);
                    float s1 = fmaf(sc[nt][r * 2 + 1], SCALE2, mk.y);
                    sc[nt][r * 2 + 0] = s0;
                    sc[nt][r * 2 + 1] = s1;
                    rmax = fmaxf(rmax, fmaxf(s0, s1));
                }
            } else {
                const int ig = i0 + m0 + rg + r * 8;
#pragma unroll
                for (int nt = 0; nt < 8; nt++) {
                    const float2 mk = *(const float2*)&smask[buf][nt * 8 + tg * 2];
#pragma unroll
                    for (int e = 0; e < 2; e++) {
                        const int jg = j0 + nt * 8 + tg * 2 + e;
                        float s = fmaf(sc[nt][r * 2 + e], SCALE2, (e == 0) ? mk.x : mk.y);
                        if (jg - ig > (WIN - 1)) s = -1e30f;
                        sc[nt][r * 2 + e] = s;
                        rmax = fmaxf(rmax, s);
                    }
                }
            }
            rmax = fmaxf(rmax, __shfl_xor_sync(0xffffffffu, rmax, 1));
            rmax = fmaxf(rmax, __shfl_xor_sync(0xffffffffu, rmax, 2));
            const float mnew = fmaxf(mrow[r], rmax);
            const float alpha = ex2(mrow[r] - mnew);
            float rsum = 0.0f;
#pragma unroll
            for (int nt = 0; nt < 8; nt++)
#pragma unroll
                for (int e = 0; e < 2; e++) {
                    const float p = ex2(sc[nt][r * 2 + e] - mnew);
                    sc[nt][r * 2 + e] = p;
                    rsum += p;
                }
            rsum += __shfl_xor_sync(0xffffffffu, rsum, 1);
            rsum += __shfl_xor_sync(0xffffffffu, rsum, 2);
            lrow[r] = lrow[r] * alpha + rsum;
            mrow[r] = mnew;
#pragma unroll
            for (int nt = 0; nt < 8; nt++) {
                o[nt][r * 2 + 0] *= alpha;
                o[nt][r * 2 + 1] *= alpha;
            }
        }

        // ---- O += P V (2-pass: ph·vh + pl·vh) ----
#pragma unroll
        for (int u = 0; u < 4; u++) {
            uint32_t ph[4], pl[4];
            split2h(sc[2 * u][0],     sc[2 * u][1],     ph[0], pl[0]);
            split2h(sc[2 * u][2],     sc[2 * u][3],     ph[1], pl[1]);
            split2h(sc[2 * u + 1][0], sc[2 * u + 1][1], ph[2], pl[2]);
            split2h(sc[2 * u + 1][2], sc[2 * u + 1][3], ph[3], pl[3]);
#pragma unroll
            for (int np = 0; np < 8; np += 2) {
                const uint32_t bd = SW((u * 16 + (g4 & 1) * 8 + (lane & 7)) * 128
                                       + (np + (g4 >> 1)) * 16);
                uint32_t th[4];
                ldsm4t(th, st + AMAT_B + bd);
                mma16816(o[np], ph, &th[0]);
                mma16816(o[np], pl, &th[0]);
                mma16816(o[np + 1], ph, &th[2]);
                mma16816(o[np + 1], pl, &th[2]);
            }
        }
    }

    // ---- epilogue: ctx split hi/lo [b,s,e] ----
#pragma unroll
    for (int r = 0; r < 2; r++) {
        const float inv = 1.0f / lrow[r];
        const int s_g = i0 + m0 + rg + r * 8;
        const size_t rowoff = ((size_t)b * NS + s_g) * D_MODEL + h * DH;
#pragma unroll
        for (int nt = 0; nt < 8; nt++) {
            uint32_t hi, lo;
            split2h(o[nt][r * 2] * inv, o[nt][r * 2 + 1] * inv, hi, lo);
            const size_t off = rowoff + nt * 8 + tg * 2;
            *(uint32_t*)(g_Ch + off) = hi;
            *(uint32_t*)(g_Cl + off) = lo;
        }
    }
}

// ---------------- host launcher ----------------
extern "C" void kernel_launch(void* const* d_in, const int* in_sizes, int n_in,
                              void* d_out, int out_size)
{
    const float* hidden = (const float*)d_in[0];
    const int* amask    = (const int*)d_in[1];
    const float* Wq     = (const float*)d_in[2];
    const float* Wk     = (const float*)d_in[3];
    const float* Wv     = (const float*)d_in[4];
    const float* Wo     = (const float*)d_in[5];
    float* out = (float*)d_out;

    static int attr_set = 0;
    if (!attr_set) {
        cudaFuncSetAttribute(gemm_mma, cudaFuncAttributeMaxDynamicSharedMemorySize, GEMM_SMEM);
        cudaFuncSetAttribute(attn_mma, cudaFuncAttributeMaxDynamicSharedMemorySize, ATTN_SMEM);
        cudaFuncSetAttribute(attn_mma, cudaFuncAttributePreferredSharedMemoryCarveout, 100);
        cudaFuncSetAttribute(gemm_mma, cudaFuncAttributePreferredSharedMemoryCarveout, 100);
        attr_set = 1;
    }

    __half *pAh, *pAl, *pCh, *pCl;
    cudaGetSymbolAddress((void**)&pAh, g_Ah);
    cudaGetSymbolAddress((void**)&pAl, g_Al);
    cudaGetSymbolAddress((void**)&pCh, g_Ch);
    cudaGetSymbolAddress((void**)&pCl, g_Cl);

    // one pad: profiler captures the 4th launch -> attn_mma
    nop_pad<<<1, 32>>>();

    // 1. fp16 convert: X split, W rounded
    convert_all<<<2 * (MROWS * D_MODEL / 4) / 256, 256>>>(hidden, Wq, Wk, Wv, Wo);

    // 2. fused QKV projection (N = 3072)
    gemm_mma<<<dim3(3 * D_MODEL / 128, MROWS / 128), 128, GEMM_SMEM>>>(pAh, pAl, 0, 0, nullptr);

    // 3. attention
    attn_mma<<<dim3(NS / 64, NHEAD, NB), 128, ATTN_SMEM>>>(amask);

    // 4. output projection (weight rows 3072..4095), f32 out
    gemm_mma<<<dim3(D_MODEL / 128, MROWS / 128), 128, GEMM_SMEM>>>(pCh, pCl, 3 * D_MODEL, 1, out);
}